// round 12
// baseline (speedup 1.0000x reference)
#include <cuda_runtime.h>
#include <cuda_bf16.h>

// ---------------- problem constants ----------------
constexpr int B_   = 128;
constexpr int S_   = 256;
constexpr int W_   = 20;
constexpr int WE_  = 300;
constexpr int CE_  = 50;
constexpr int CC_  = 100;
constexpr int CV_  = 100;
constexpr int H_   = 256;     // per-direction hidden
constexpr int DIN_ = 400;     // WE + CC
constexpr int T_   = 12;
constexpr int START_ = 9, STOP_ = 10, PAD_ = 11;

// ---------------- scratch (device globals; no allocation allowed) ----------
__device__ float g_P[3 * CV_ * CC_];            // [k][v][c] conv response table
__device__ float g_xs[S_ * B_ * DIN_];          // embeddings, [s][b][din]
__device__ float g_xproj[S_ * B_ * 2048];       // input projection, [s][b][2*1024]
__device__ float g_h[2][S_ * B_ * H_];          // lstm hidden, [dir][s][b][h]
__device__ float g_hbuf[2 * 2 * B_ * H_];       // double-buffered h, [parity][dir][b][h]
__device__ float g_feats[S_ * B_ * T_];         // [s][b][t]
__device__ int   g_cnt[8];                      // group sync counters [dir*4+bt]

__device__ __forceinline__ float sigf(float x) { return 1.0f / (1.0f + expf(-x)); }

// ---------------- K1: precompute conv response table + reset counters ------
__global__ void k_prep(const float* __restrict__ char_table,
                       const float* __restrict__ conv_w)
{
    int blk = blockIdx.x;            // 0..299
    int k = blk / CV_, v = blk % CV_;
    int c = threadIdx.x;
    if (blk == 0 && c < 8) g_cnt[c] = 0;
    if (c < CC_) {
        float s = 0.f;
        #pragma unroll 10
        for (int e = 0; e < CE_; e++)
            s += char_table[v * CE_ + e] * conv_w[c * CE_ * 3 + e * 3 + k];
        g_P[(k * CV_ + v) * CC_ + c] = s;
    }
}

// ---------------- K2: word-emb gather + char conv/relu/maxpool -------------
__global__ void k_embed(const int* __restrict__ word_idxs,
                        const int* __restrict__ char_idxs,
                        const float* __restrict__ word_table,
                        const float* __restrict__ conv_b)
{
    int bs = blockIdx.x;             // b*S + s
    int b = bs >> 8, s = bs & 255;
    int tid = threadIdx.x;
    __shared__ int ch[W_];
    int wi = word_idxs[b * S_ + s];
    float* dst = &g_xs[(s * B_ + b) * DIN_];
    for (int i = tid; i < WE_; i += 128)
        dst[i] = word_table[wi * WE_ + i];
    if (tid < W_) ch[tid] = char_idxs[(b * S_ + s) * W_ + tid];
    __syncthreads();
    if (tid < CC_) {
        int c = tid;
        float bb = conv_b[c];
        float m = -3.4e38f;
        #pragma unroll
        for (int w = 0; w < W_; w++) {
            float v = bb;
            if (w > 0)      v += g_P[(0 * CV_ + ch[w - 1]) * CC_ + c];
            v += g_P[(1 * CV_ + ch[w]) * CC_ + c];
            if (w < W_ - 1) v += g_P[(2 * CV_ + ch[w + 1]) * CC_ + c];
            m = fmaxf(m, v);
        }
        dst[WE_ + c] = fmaxf(m, 0.0f);   // max of relu == relu of max
    }
}

// ---------------- K3: input projection GEMM --------------------------------
// C[m, n] = xs[m, :] . w_ih[n, :] + (b_ih + b_hh)[n]
// m = s*B+b (32768), n in [0,2048): n<1024 forward dir, else backward.
__global__ void __launch_bounds__(256) k_gemm(
    const float* __restrict__ wf, const float* __restrict__ wb,
    const float* __restrict__ bihf, const float* __restrict__ bhhf,
    const float* __restrict__ bihb, const float* __restrict__ bhhb)
{
    __shared__ float As[8][128];
    __shared__ float Bs[8][128];
    int tid = threadIdx.x;
    int m0 = blockIdx.y * 128;
    int n0 = blockIdx.x * 128;
    int lrow = tid >> 1;
    int kq = (tid & 1) * 4;
    const float* aptr = &g_xs[(m0 + lrow) * DIN_ + kq];
    int nrow = n0 + lrow;
    const float* bptr = (nrow < 1024) ? (wf + nrow * DIN_ + kq)
                                      : (wb + (nrow - 1024) * DIN_ + kq);
    int ty = tid >> 4, tx = tid & 15;
    float acc[8][8];
    #pragma unroll
    for (int i = 0; i < 8; i++)
        #pragma unroll
        for (int j = 0; j < 8; j++) acc[i][j] = 0.f;

    for (int k0 = 0; k0 < DIN_; k0 += 8) {
        float4 av = *(const float4*)(aptr + k0);
        float4 bv = *(const float4*)(bptr + k0);
        __syncthreads();
        As[kq + 0][lrow] = av.x; As[kq + 1][lrow] = av.y;
        As[kq + 2][lrow] = av.z; As[kq + 3][lrow] = av.w;
        Bs[kq + 0][lrow] = bv.x; Bs[kq + 1][lrow] = bv.y;
        Bs[kq + 2][lrow] = bv.z; Bs[kq + 3][lrow] = bv.w;
        __syncthreads();
        #pragma unroll
        for (int kk = 0; kk < 8; kk++) {
            float4 a0 = *(const float4*)&As[kk][ty * 8];
            float4 a1 = *(const float4*)&As[kk][ty * 8 + 4];
            float4 b0 = *(const float4*)&Bs[kk][tx * 8];
            float4 b1 = *(const float4*)&Bs[kk][tx * 8 + 4];
            float a[8] = {a0.x, a0.y, a0.z, a0.w, a1.x, a1.y, a1.z, a1.w};
            float bb[8] = {b0.x, b0.y, b0.z, b0.w, b1.x, b1.y, b1.z, b1.w};
            #pragma unroll
            for (int i = 0; i < 8; i++)
                #pragma unroll
                for (int j = 0; j < 8; j++)
                    acc[i][j] = fmaf(a[i], bb[j], acc[i][j]);
        }
    }
    float bj[8];
    #pragma unroll
    for (int j = 0; j < 8; j++) {
        int n2 = n0 + tx * 8 + j;
        bj[j] = (n2 < 1024) ? (bihf[n2] + bhhf[n2])
                            : (bihb[n2 - 1024] + bhhb[n2 - 1024]);
    }
    #pragma unroll
    for (int i = 0; i < 8; i++) {
        float* rowp = &g_xproj[(size_t)(m0 + ty * 8 + i) * 2048 + n0 + tx * 8];
        #pragma unroll
        for (int j = 0; j < 8; j++) rowp[j] = acc[i][j] + bj[j];
    }
}

// ---------------- K4: bidirectional LSTM recurrence ------------------------
// Grid: 128 CTAs = dir(2) x batch-tile(4, 32 each) x h-slice(16, 16 units each).
// Each CTA keeps its 64-row w_hh slice (64KB) in smem for all 256 steps.
// Cross-CTA sync within each (dir, batch-tile) group of 16 via atomic counter.
constexpr int LSTM_SMEM = (64 * 256 + 256 * 33 + 32 * 65) * 4;  // 107648 B

__global__ void __launch_bounds__(256) k_lstm(const float* __restrict__ whhf,
                                              const float* __restrict__ whhb)
{
    extern __shared__ float sm[];
    float* w_s = sm;                       // [64][256]
    float* h_s = sm + 64 * 256;            // transposed [256][33] (padded)
    float* x_s = h_s + 256 * 33;           // [32][65]   (padded)

    int tid  = threadIdx.x;
    int dir  = blockIdx.x >> 6;
    int bt   = (blockIdx.x >> 4) & 3;
    int hs   = blockIdx.x & 15;
    int bsub = tid & 31;
    int uq   = tid >> 5;                   // 0..7 -> units uq*2, uq*2+1
    const float* whh = dir ? whhb : whhf;

    // weights: local row r = g*16+u  ->  global row g*256 + hs*16 + u
    for (int idx = tid; idx < 64 * 256; idx += 256) {
        int row = idx >> 8, k = idx & 255;
        int g = row >> 4, u = row & 15;
        w_s[idx] = whh[(g * H_ + hs * 16 + u) * H_ + k];
    }

    int bglob = bt * 32 + bsub;
    int ub0 = hs * 16 + uq * 2;
    // zero-init h(-1): parity 1
    {
        float* hb1 = &g_hbuf[((1 * 2 + dir) * B_ + bglob) * H_];
        hb1[ub0] = 0.f; hb1[ub0 + 1] = 0.f;
    }
    __threadfence();
    __syncthreads();
    if (tid == 0) atomicAdd(&g_cnt[dir * 4 + bt], 1);

    int rowoff[8], colidx[8];
    #pragma unroll
    for (int a = 0; a < 8; a++) {
        int g = a & 3, uu = a >> 2;
        int r = g * 16 + uq * 2 + uu;
        rowoff[a] = r * 256;
        colidx[a] = r;
    }
    float c0 = 0.f, c1 = 0.f;
    volatile int* cntp = &g_cnt[dir * 4 + bt];

    for (int t = 0; t < S_; t++) {
        int s = dir ? (S_ - 1 - t) : t;
        if (tid == 0) { while (*cntp < 16 * (t + 1)) { } }
        __syncthreads();
        __threadfence();

        // stage h(t-1) [parity (t+1)&1], transposed; L2 loads (skip stale L1)
        {
            const float* src = &g_hbuf[(((t + 1) & 1) * 2 + dir) * B_ * H_ + bt * 32 * H_];
            for (int i = tid; i < 32 * (H_ / 4); i += 256) {
                int bloc = i >> 6;
                int k4 = (i & 63) * 4;
                float4 hv = __ldcg((const float4*)(src + bloc * H_ + k4));
                h_s[(k4 + 0) * 33 + bloc] = hv.x;
                h_s[(k4 + 1) * 33 + bloc] = hv.y;
                h_s[(k4 + 2) * 33 + bloc] = hv.z;
                h_s[(k4 + 3) * 33 + bloc] = hv.w;
            }
            const float* xp = &g_xproj[(size_t)(s * B_ + bt * 32) * 2048 + dir * 1024];
            for (int i = tid; i < 32 * 64; i += 256) {
                int bloc = i >> 6, j = i & 63;
                int g = j >> 4, u = j & 15;
                x_s[bloc * 65 + j] = xp[(size_t)bloc * 2048 + g * H_ + hs * 16 + u];
            }
        }
        __syncthreads();

        float acc[8];
        #pragma unroll
        for (int a = 0; a < 8; a++) acc[a] = x_s[bsub * 65 + colidx[a]];

        #pragma unroll 8
        for (int kk = 0; kk < 256; kk += 4) {
            float h0 = h_s[(kk + 0) * 33 + bsub];
            float h1 = h_s[(kk + 1) * 33 + bsub];
            float h2 = h_s[(kk + 2) * 33 + bsub];
            float h3 = h_s[(kk + 3) * 33 + bsub];
            #pragma unroll
            for (int a = 0; a < 8; a++) {
                float4 w = *(const float4*)&w_s[rowoff[a] + kk];
                acc[a] = fmaf(w.x, h0, acc[a]);
                acc[a] = fmaf(w.y, h1, acc[a]);
                acc[a] = fmaf(w.z, h2, acc[a]);
                acc[a] = fmaf(w.w, h3, acc[a]);
            }
        }

        float* hb_out = &g_hbuf[((t & 1) * 2 + dir) * B_ * H_ + bglob * H_];
        float* h_out  = &g_h[dir][(size_t)(s * B_ + bglob) * H_];
        #pragma unroll
        for (int uu = 0; uu < 2; uu++) {
            float ig = sigf(acc[uu * 4 + 0]);
            float fg = sigf(acc[uu * 4 + 1]);
            float gg = tanhf(acc[uu * 4 + 2]);
            float og = sigf(acc[uu * 4 + 3]);
            float cc = (uu ? c1 : c0);
            cc = fg * cc + ig * gg;
            if (uu) c1 = cc; else c0 = cc;
            float hv = og * tanhf(cc);
            hb_out[ub0 + uu] = hv;
            h_out[ub0 + uu]  = hv;
        }
        __threadfence();
        __syncthreads();
        if (tid == 0) atomicAdd(&g_cnt[dir * 4 + bt], 1);
    }
}

// ---------------- K5: feats = [h_f, h_b] @ h2t_w^T + h2t_b -----------------
__global__ void __launch_bounds__(256) k_feats(const float* __restrict__ h2t_w,
                                               const float* __restrict__ h2t_b)
{
    __shared__ float w_s[T_ * 512];
    __shared__ float b_s[T_];
    int tid = threadIdx.x;
    for (int i = tid; i < T_ * 512; i += 256) w_s[i] = h2t_w[i];
    if (tid < T_) b_s[tid] = h2t_b[tid];
    __syncthreads();
    int wid = tid >> 5, lane = tid & 31;
    int m = blockIdx.x * 8 + wid;          // m = s*B + b
    const float* hf  = &g_h[0][(size_t)m * H_];
    const float* hbk = &g_h[1][(size_t)m * H_];
    float hr[16];
    #pragma unroll
    for (int i = 0; i < 8; i++) hr[i]     = hf[lane + 32 * i];
    #pragma unroll
    for (int i = 0; i < 8; i++) hr[8 + i] = hbk[lane + 32 * i];
    for (int t = 0; t < T_; t++) {
        float a = 0.f;
        #pragma unroll
        for (int i = 0; i < 8; i++)
            a = fmaf(hr[i], w_s[t * 512 + lane + 32 * i], a);
        #pragma unroll
        for (int i = 0; i < 8; i++)
            a = fmaf(hr[8 + i], w_s[t * 512 + 256 + lane + 32 * i], a);
        #pragma unroll
        for (int off = 16; off; off >>= 1)
            a += __shfl_xor_sync(0xffffffff, a, off);
        if (lane == 0) g_feats[m * T_ + t] = a + b_s[t];
    }
}

// ---------------- K6: batched Viterbi + backtrace --------------------------
__global__ void k_viterbi(const int* __restrict__ mask,
                          const float* __restrict__ trans,
                          float* __restrict__ out)
{
    int b = blockIdx.x;
    int lane = threadIdx.x;                 // 32 threads
    __shared__ float tr[T_ * T_];
    __shared__ float alpha[T_];
    __shared__ float alpha2[T_];
    __shared__ unsigned char bps[S_ * T_];
    __shared__ int msk[S_];
    for (int i = lane; i < T_ * T_; i += 32) tr[i] = trans[i];
    for (int i = lane; i < S_; i += 32) msk[i] = mask[b * S_ + i];
    if (lane < T_) alpha[lane] = (lane == START_) ? 0.0f : -10000.0f;
    __syncwarp();
    for (int s = 0; s < S_; s++) {
        float na = 0.f; int bi = 0;
        if (lane < T_) {
            float f = g_feats[(s * B_ + b) * T_ + lane];
            float best = -3.4e38f;
            #pragma unroll
            for (int p = 0; p < T_; p++) {
                float sc = (alpha[p] + tr[p * T_ + lane]) + f;  // same assoc as ref
                if (sc > best) { best = sc; bi = p; }           // first-max tie-break
            }
            bps[s * T_ + lane] = (unsigned char)bi;
            na = msk[s] ? best : alpha[lane];
        }
        __syncwarp();
        if (lane < T_) alpha[lane] = na;
        __syncwarp();
    }
    if (lane < T_) alpha2[lane] = alpha[lane] + tr[STOP_ * T_ + lane];
    __syncwarp();
    if (lane == 0) {
        float best = -3.4e38f; int bl = 0;
        for (int t = 0; t < T_; t++)
            if (alpha2[t] > best) { best = alpha2[t]; bl = t; }
        out[b] = best;
        int tag = bl;
        for (int i = S_ - 1; i >= 0; i--) {
            int valid = msk[i];
            int o = valid ? tag : PAD_;
            out[B_ + b * S_ + i] = (float)o;
            int prev = bps[i * T_ + tag];
            tag = valid ? prev : tag;
        }
    }
}

// ---------------- launch ---------------------------------------------------
extern "C" void kernel_launch(void* const* d_in, const int* in_sizes, int n_in,
                              void* d_out, int out_size)
{
    const int*   word_idxs  = (const int*)d_in[0];
    const int*   char_idxs  = (const int*)d_in[1];
    const int*   mask       = (const int*)d_in[2];
    const float* word_table = (const float*)d_in[3];
    const float* char_table = (const float*)d_in[4];
    const float* conv_w     = (const float*)d_in[5];
    const float* conv_b     = (const float*)d_in[6];
    const float* w_ih_f     = (const float*)d_in[7];
    const float* w_hh_f     = (const float*)d_in[8];
    const float* b_ih_f     = (const float*)d_in[9];
    const float* b_hh_f     = (const float*)d_in[10];
    const float* w_ih_b     = (const float*)d_in[11];
    const float* w_hh_b     = (const float*)d_in[12];
    const float* b_ih_b     = (const float*)d_in[13];
    const float* b_hh_b     = (const float*)d_in[14];
    const float* h2t_w      = (const float*)d_in[15];
    const float* h2t_b      = (const float*)d_in[16];
    const float* trans      = (const float*)d_in[17];
    float* out = (float*)d_out;

    cudaFuncSetAttribute(k_lstm, cudaFuncAttributeMaxDynamicSharedMemorySize, LSTM_SMEM);

    k_prep<<<3 * CV_, 128>>>(char_table, conv_w);
    k_embed<<<B_ * S_, 128>>>(word_idxs, char_idxs, word_table, conv_b);
    dim3 g3(16, 256);   // n-tiles x m-tiles
    k_gemm<<<g3, 256>>>(w_ih_f, w_ih_b, b_ih_f, b_hh_f, b_ih_b, b_hh_b);
    k_lstm<<<128, 256, LSTM_SMEM>>>(w_hh_f, w_hh_b);
    k_feats<<<(B_ * S_) / 8, 256>>>(h2t_w, h2t_b);
    k_viterbi<<<B_, 32>>>(mask, trans, out);
}

// round 13
// speedup vs baseline: 1.2484x; 1.2484x over previous
#include <cuda_runtime.h>
#include <cuda_bf16.h>

// ---------------- problem constants ----------------
constexpr int B_   = 128;
constexpr int S_   = 256;
constexpr int W_   = 20;
constexpr int WE_  = 300;
constexpr int CE_  = 50;
constexpr int CC_  = 100;
constexpr int CV_  = 100;
constexpr int H_   = 256;     // per-direction hidden
constexpr int DIN_ = 400;     // WE + CC
constexpr int T_   = 12;
constexpr int START_ = 9, STOP_ = 10, PAD_ = 11;

// ---------------- scratch (device globals; no allocation allowed) ----------
__device__ float g_P[3 * CV_ * CC_];            // [k][v][c] conv response table
__device__ __nv_bfloat16 g_xs_hi[S_ * B_ * DIN_];   // split embeddings (hi)
__device__ __nv_bfloat16 g_xs_lo[S_ * B_ * DIN_];   // split embeddings (lo)
__device__ __nv_bfloat16 g_w_hi[2048 * DIN_];       // split w_ih (f then b), hi
__device__ __nv_bfloat16 g_w_lo[2048 * DIN_];       // split w_ih, lo
__device__ float g_xproj[S_ * B_ * 2048];       // input projection, [s][b][2*1024]
__device__ float g_h[2][S_ * B_ * H_];          // lstm hidden, [dir][s][b][h]
__device__ float g_hbuf[2 * 2 * B_ * H_];       // double-buffered h, [parity][dir][b][h]
__device__ float g_feats[S_ * B_ * T_];         // [s][b][t]
__device__ int   g_cnt[8];                      // group sync counters [dir*4+bt]

__device__ __forceinline__ float sigf(float x) { return 1.0f / (1.0f + expf(-x)); }

__device__ __forceinline__ void split_store(float v, __nv_bfloat16* hi, __nv_bfloat16* lo)
{
    __nv_bfloat16 h = __float2bfloat16(v);
    *hi = h;
    *lo = __float2bfloat16(v - __bfloat162float(h));
}

// ---------------- K1: precompute conv response table + reset counters ------
__global__ void k_prep(const float* __restrict__ char_table,
                       const float* __restrict__ conv_w)
{
    int blk = blockIdx.x;            // 0..299
    int k = blk / CV_, v = blk % CV_;
    int c = threadIdx.x;
    if (blk == 0 && c < 8) g_cnt[c] = 0;
    if (c < CC_) {
        float s = 0.f;
        #pragma unroll 10
        for (int e = 0; e < CE_; e++)
            s += char_table[v * CE_ + e] * conv_w[c * CE_ * 3 + e * 3 + k];
        g_P[(k * CV_ + v) * CC_ + c] = s;
    }
}

// ---------------- K1b: split w_ih into bf16 hi/lo --------------------------
__global__ void k_prep_w(const float* __restrict__ wf, const float* __restrict__ wb)
{
    int n = blockIdx.x;              // 0..2047
    const float* src = (n < 1024) ? (wf + n * DIN_) : (wb + (n - 1024) * DIN_);
    for (int i = threadIdx.x; i < DIN_; i += blockDim.x)
        split_store(src[i], &g_w_hi[n * DIN_ + i], &g_w_lo[n * DIN_ + i]);
}

// ---------------- K2: word-emb gather + char conv/relu/maxpool -------------
__global__ void k_embed(const int* __restrict__ word_idxs,
                        const int* __restrict__ char_idxs,
                        const float* __restrict__ word_table,
                        const float* __restrict__ conv_b)
{
    int bs = blockIdx.x;             // b*S + s
    int b = bs >> 8, s = bs & 255;
    int tid = threadIdx.x;
    __shared__ int ch[W_];
    int wi = word_idxs[b * S_ + s];
    size_t base = (size_t)(s * B_ + b) * DIN_;
    for (int i = tid; i < WE_; i += 128)
        split_store(word_table[wi * WE_ + i], &g_xs_hi[base + i], &g_xs_lo[base + i]);
    if (tid < W_) ch[tid] = char_idxs[(b * S_ + s) * W_ + tid];
    __syncthreads();
    if (tid < CC_) {
        int c = tid;
        float bb = conv_b[c];
        float m = -3.4e38f;
        #pragma unroll
        for (int w = 0; w < W_; w++) {
            float v = bb;
            if (w > 0)      v += g_P[(0 * CV_ + ch[w - 1]) * CC_ + c];
            v += g_P[(1 * CV_ + ch[w]) * CC_ + c];
            if (w < W_ - 1) v += g_P[(2 * CV_ + ch[w + 1]) * CC_ + c];
            m = fmaxf(m, v);
        }
        float val = fmaxf(m, 0.0f);  // max of relu == relu of max
        split_store(val, &g_xs_hi[base + WE_ + c], &g_xs_lo[base + WE_ + c]);
    }
}

// ---------------- K3: input projection GEMM (tensor cores, split-bf16) -----
// C[m, n] = xs[m, :] . w_ih[n, :] + (b_ih + b_hh)[n]
// m = s*B+b (32768), n in [0,2048). CTA tile 128x128, BK=16, 8 warps (2m x 4n),
// warp tile 64x32. Split precision: C = xhi*whi + xhi*wlo + xlo*whi (fp32 acc).
constexpr int GSTR = 24;  // padded smem row (bf16 elems): conflict-free fragments

__device__ __forceinline__ void mma16816(float* c, const unsigned* a, const unsigned* b)
{
    asm volatile(
        "mma.sync.aligned.m16n8k16.row.col.f32.bf16.bf16.f32 "
        "{%0,%1,%2,%3}, {%4,%5,%6,%7}, {%8,%9}, {%0,%1,%2,%3};\n"
        : "+f"(c[0]), "+f"(c[1]), "+f"(c[2]), "+f"(c[3])
        : "r"(a[0]), "r"(a[1]), "r"(a[2]), "r"(a[3]), "r"(b[0]), "r"(b[1]));
}

__global__ void __launch_bounds__(256) k_gemm_mma(
    const float* __restrict__ bihf, const float* __restrict__ bhhf,
    const float* __restrict__ bihb, const float* __restrict__ bhhb)
{
    __shared__ __nv_bfloat16 sAhi[128 * GSTR], sAlo[128 * GSTR];
    __shared__ __nv_bfloat16 sBhi[128 * GSTR], sBlo[128 * GSTR];
    __shared__ float sBias[128];

    int tid = threadIdx.x;
    int m0 = blockIdx.y * 128;
    int n0 = blockIdx.x * 128;
    int wid = tid >> 5, lane = tid & 31;
    int warp_m = wid >> 2, warp_n = wid & 3;

    if (tid < 128) {
        int n2 = n0 + tid;
        sBias[tid] = (n2 < 1024) ? (bihf[n2] + bhhf[n2])
                                 : (bihb[n2 - 1024] + bhhb[n2 - 1024]);
    }

    int r = tid >> 1, part = tid & 1;
    size_t a_off = (size_t)(m0 + r) * DIN_ + part * 8;
    size_t b_off = (size_t)(n0 + r) * DIN_ + part * 8;
    int s_off = r * GSTR + part * 8;

    float acc[4][4][4];
    #pragma unroll
    for (int mi = 0; mi < 4; mi++)
        #pragma unroll
        for (int ni = 0; ni < 4; ni++)
            #pragma unroll
            for (int q = 0; q < 4; q++) acc[mi][ni][q] = 0.f;

    int qr = lane >> 2, kp = (lane & 3) * 2;

    for (int k0 = 0; k0 < DIN_; k0 += 16) {
        uint4 vah = *(const uint4*)&g_xs_hi[a_off + k0];
        uint4 val = *(const uint4*)&g_xs_lo[a_off + k0];
        uint4 vbh = *(const uint4*)&g_w_hi[b_off + k0];
        uint4 vbl = *(const uint4*)&g_w_lo[b_off + k0];
        __syncthreads();
        *(uint4*)&sAhi[s_off] = vah;
        *(uint4*)&sAlo[s_off] = val;
        *(uint4*)&sBhi[s_off] = vbh;
        *(uint4*)&sBlo[s_off] = vbl;
        __syncthreads();

        unsigned ahi[4][4], alo[4][4], bhi[4][2], blo[4][2];
        #pragma unroll
        for (int mi = 0; mi < 4; mi++) {
            int rr = warp_m * 64 + mi * 16 + qr;
            ahi[mi][0] = *(const unsigned*)&sAhi[rr * GSTR + kp];
            ahi[mi][1] = *(const unsigned*)&sAhi[(rr + 8) * GSTR + kp];
            ahi[mi][2] = *(const unsigned*)&sAhi[rr * GSTR + kp + 8];
            ahi[mi][3] = *(const unsigned*)&sAhi[(rr + 8) * GSTR + kp + 8];
            alo[mi][0] = *(const unsigned*)&sAlo[rr * GSTR + kp];
            alo[mi][1] = *(const unsigned*)&sAlo[(rr + 8) * GSTR + kp];
            alo[mi][2] = *(const unsigned*)&sAlo[rr * GSTR + kp + 8];
            alo[mi][3] = *(const unsigned*)&sAlo[(rr + 8) * GSTR + kp + 8];
        }
        #pragma unroll
        for (int ni = 0; ni < 4; ni++) {
            int cc = warp_n * 32 + ni * 8 + qr;
            bhi[ni][0] = *(const unsigned*)&sBhi[cc * GSTR + kp];
            bhi[ni][1] = *(const unsigned*)&sBhi[cc * GSTR + kp + 8];
            blo[ni][0] = *(const unsigned*)&sBlo[cc * GSTR + kp];
            blo[ni][1] = *(const unsigned*)&sBlo[cc * GSTR + kp + 8];
        }
        #pragma unroll
        for (int mi = 0; mi < 4; mi++)
            #pragma unroll
            for (int ni = 0; ni < 4; ni++)
                mma16816(acc[mi][ni], ahi[mi], bhi[ni]);
        #pragma unroll
        for (int mi = 0; mi < 4; mi++)
            #pragma unroll
            for (int ni = 0; ni < 4; ni++)
                mma16816(acc[mi][ni], ahi[mi], blo[ni]);
        #pragma unroll
        for (int mi = 0; mi < 4; mi++)
            #pragma unroll
            for (int ni = 0; ni < 4; ni++)
                mma16816(acc[mi][ni], alo[mi], bhi[ni]);
    }

    #pragma unroll
    for (int mi = 0; mi < 4; mi++) {
        int rr = warp_m * 64 + mi * 16 + qr;
        #pragma unroll
        for (int ni = 0; ni < 4; ni++) {
            int cc = warp_n * 32 + ni * 8 + kp;
            float b0 = sBias[cc], b1 = sBias[cc + 1];
            float* p = &g_xproj[(size_t)(m0 + rr) * 2048 + n0 + cc];
            float2 v0 = make_float2(acc[mi][ni][0] + b0, acc[mi][ni][1] + b1);
            float2 v1 = make_float2(acc[mi][ni][2] + b0, acc[mi][ni][3] + b1);
            *(float2*)p = v0;
            *(float2*)(p + 8 * 2048) = v1;
        }
    }
}

// ---------------- K4: bidirectional LSTM recurrence ------------------------
// Grid: 128 CTAs = dir(2) x batch-tile(4, 32 each) x h-slice(16, 16 units each).
// Each CTA keeps its 64-row w_hh slice (64KB) in smem for all 256 steps.
// Cross-CTA sync within each (dir, batch-tile) group of 16 via atomic counter.
constexpr int LSTM_SMEM = (64 * 256 + 256 * 33 + 32 * 65) * 4;  // 107648 B

__global__ void __launch_bounds__(256) k_lstm(const float* __restrict__ whhf,
                                              const float* __restrict__ whhb)
{
    extern __shared__ float sm[];
    float* w_s = sm;                       // [64][256]
    float* h_s = sm + 64 * 256;            // transposed [256][33] (padded)
    float* x_s = h_s + 256 * 33;           // [32][65]   (padded)

    int tid  = threadIdx.x;
    int dir  = blockIdx.x >> 6;
    int bt   = (blockIdx.x >> 4) & 3;
    int hs   = blockIdx.x & 15;
    int bsub = tid & 31;
    int uq   = tid >> 5;                   // 0..7 -> units uq*2, uq*2+1
    const float* whh = dir ? whhb : whhf;

    // weights: local row r = g*16+u  ->  global row g*256 + hs*16 + u
    for (int idx = tid; idx < 64 * 256; idx += 256) {
        int row = idx >> 8, k = idx & 255;
        int g = row >> 4, u = row & 15;
        w_s[idx] = whh[(g * H_ + hs * 16 + u) * H_ + k];
    }

    int bglob = bt * 32 + bsub;
    int ub0 = hs * 16 + uq * 2;
    // zero-init h(-1): parity 1
    {
        float* hb1 = &g_hbuf[((1 * 2 + dir) * B_ + bglob) * H_];
        hb1[ub0] = 0.f; hb1[ub0 + 1] = 0.f;
    }
    __threadfence();
    __syncthreads();
    if (tid == 0) atomicAdd(&g_cnt[dir * 4 + bt], 1);

    int rowoff[8], colidx[8];
    #pragma unroll
    for (int a = 0; a < 8; a++) {
        int g = a & 3, uu = a >> 2;
        int r = g * 16 + uq * 2 + uu;
        rowoff[a] = r * 256;
        colidx[a] = r;
    }
    float c0 = 0.f, c1 = 0.f;
    volatile int* cntp = &g_cnt[dir * 4 + bt];

    for (int t = 0; t < S_; t++) {
        int s = dir ? (S_ - 1 - t) : t;
        if (tid == 0) { while (*cntp < 16 * (t + 1)) { } }
        __syncthreads();
        __threadfence();

        // stage h(t-1) [parity (t+1)&1], transposed; L2 loads (skip stale L1)
        {
            const float* src = &g_hbuf[(((t + 1) & 1) * 2 + dir) * B_ * H_ + bt * 32 * H_];
            for (int i = tid; i < 32 * (H_ / 4); i += 256) {
                int bloc = i >> 6;
                int k4 = (i & 63) * 4;
                float4 hv = __ldcg((const float4*)(src + bloc * H_ + k4));
                h_s[(k4 + 0) * 33 + bloc] = hv.x;
                h_s[(k4 + 1) * 33 + bloc] = hv.y;
                h_s[(k4 + 2) * 33 + bloc] = hv.z;
                h_s[(k4 + 3) * 33 + bloc] = hv.w;
            }
            const float* xp = &g_xproj[(size_t)(s * B_ + bt * 32) * 2048 + dir * 1024];
            for (int i = tid; i < 32 * 64; i += 256) {
                int bloc = i >> 6, j = i & 63;
                int g = j >> 4, u = j & 15;
                x_s[bloc * 65 + j] = xp[(size_t)bloc * 2048 + g * H_ + hs * 16 + u];
            }
        }
        __syncthreads();

        float acc[8];
        #pragma unroll
        for (int a = 0; a < 8; a++) acc[a] = x_s[bsub * 65 + colidx[a]];

        #pragma unroll 8
        for (int kk = 0; kk < 256; kk += 4) {
            float h0 = h_s[(kk + 0) * 33 + bsub];
            float h1 = h_s[(kk + 1) * 33 + bsub];
            float h2 = h_s[(kk + 2) * 33 + bsub];
            float h3 = h_s[(kk + 3) * 33 + bsub];
            #pragma unroll
            for (int a = 0; a < 8; a++) {
                float4 w = *(const float4*)&w_s[rowoff[a] + kk];
                acc[a] = fmaf(w.x, h0, acc[a]);
                acc[a] = fmaf(w.y, h1, acc[a]);
                acc[a] = fmaf(w.z, h2, acc[a]);
                acc[a] = fmaf(w.w, h3, acc[a]);
            }
        }

        float* hb_out = &g_hbuf[((t & 1) * 2 + dir) * B_ * H_ + bglob * H_];
        float* h_out  = &g_h[dir][(size_t)(s * B_ + bglob) * H_];
        #pragma unroll
        for (int uu = 0; uu < 2; uu++) {
            float ig = sigf(acc[uu * 4 + 0]);
            float fg = sigf(acc[uu * 4 + 1]);
            float gg = tanhf(acc[uu * 4 + 2]);
            float og = sigf(acc[uu * 4 + 3]);
            float cc = (uu ? c1 : c0);
            cc = fg * cc + ig * gg;
            if (uu) c1 = cc; else c0 = cc;
            float hv = og * tanhf(cc);
            hb_out[ub0 + uu] = hv;
            h_out[ub0 + uu]  = hv;
        }
        __threadfence();
        __syncthreads();
        if (tid == 0) atomicAdd(&g_cnt[dir * 4 + bt], 1);
    }
}

// ---------------- K5: feats = [h_f, h_b] @ h2t_w^T + h2t_b -----------------
__global__ void __launch_bounds__(256) k_feats(const float* __restrict__ h2t_w,
                                               const float* __restrict__ h2t_b)
{
    __shared__ float w_s[T_ * 512];
    __shared__ float b_s[T_];
    int tid = threadIdx.x;
    for (int i = tid; i < T_ * 512; i += 256) w_s[i] = h2t_w[i];
    if (tid < T_) b_s[tid] = h2t_b[tid];
    __syncthreads();
    int wid = tid >> 5, lane = tid & 31;
    int m = blockIdx.x * 8 + wid;          // m = s*B + b
    const float* hf  = &g_h[0][(size_t)m * H_];
    const float* hbk = &g_h[1][(size_t)m * H_];
    float hr[16];
    #pragma unroll
    for (int i = 0; i < 8; i++) hr[i]     = hf[lane + 32 * i];
    #pragma unroll
    for (int i = 0; i < 8; i++) hr[8 + i] = hbk[lane + 32 * i];
    for (int t = 0; t < T_; t++) {
        float a = 0.f;
        #pragma unroll
        for (int i = 0; i < 8; i++)
            a = fmaf(hr[i], w_s[t * 512 + lane + 32 * i], a);
        #pragma unroll
        for (int i = 0; i < 8; i++)
            a = fmaf(hr[8 + i], w_s[t * 512 + 256 + lane + 32 * i], a);
        #pragma unroll
        for (int off = 16; off; off >>= 1)
            a += __shfl_xor_sync(0xffffffff, a, off);
        if (lane == 0) g_feats[m * T_ + t] = a + b_s[t];
    }
}

// ---------------- K6: batched Viterbi + backtrace --------------------------
__global__ void k_viterbi(const int* __restrict__ mask,
                          const float* __restrict__ trans,
                          float* __restrict__ out)
{
    int b = blockIdx.x;
    int lane = threadIdx.x;                 // 32 threads
    __shared__ float tr[T_ * T_];
    __shared__ float alpha[T_];
    __shared__ float alpha2[T_];
    __shared__ unsigned char bps[S_ * T_];
    __shared__ int msk[S_];
    for (int i = lane; i < T_ * T_; i += 32) tr[i] = trans[i];
    for (int i = lane; i < S_; i += 32) msk[i] = mask[b * S_ + i];
    if (lane < T_) alpha[lane] = (lane == START_) ? 0.0f : -10000.0f;
    __syncwarp();
    for (int s = 0; s < S_; s++) {
        float na = 0.f; int bi = 0;
        if (lane < T_) {
            float f = g_feats[(s * B_ + b) * T_ + lane];
            float best = -3.4e38f;
            #pragma unroll
            for (int p = 0; p < T_; p++) {
                float sc = (alpha[p] + tr[p * T_ + lane]) + f;  // same assoc as ref
                if (sc > best) { best = sc; bi = p; }           // first-max tie-break
            }
            bps[s * T_ + lane] = (unsigned char)bi;
            na = msk[s] ? best : alpha[lane];
        }
        __syncwarp();
        if (lane < T_) alpha[lane] = na;
        __syncwarp();
    }
    if (lane < T_) alpha2[lane] = alpha[lane] + tr[STOP_ * T_ + lane];
    __syncwarp();
    if (lane == 0) {
        float best = -3.4e38f; int bl = 0;
        for (int t = 0; t < T_; t++)
            if (alpha2[t] > best) { best = alpha2[t]; bl = t; }
        out[b] = best;
        int tag = bl;
        for (int i = S_ - 1; i >= 0; i--) {
            int valid = msk[i];
            int o = valid ? tag : PAD_;
            out[B_ + b * S_ + i] = (float)o;
            int prev = bps[i * T_ + tag];
            tag = valid ? prev : tag;
        }
    }
}

// ---------------- launch ---------------------------------------------------
extern "C" void kernel_launch(void* const* d_in, const int* in_sizes, int n_in,
                              void* d_out, int out_size)
{
    const int*   word_idxs  = (const int*)d_in[0];
    const int*   char_idxs  = (const int*)d_in[1];
    const int*   mask       = (const int*)d_in[2];
    const float* word_table = (const float*)d_in[3];
    const float* char_table = (const float*)d_in[4];
    const float* conv_w     = (const float*)d_in[5];
    const float* conv_b     = (const float*)d_in[6];
    const float* w_ih_f     = (const float*)d_in[7];
    const float* w_hh_f     = (const float*)d_in[8];
    const float* b_ih_f     = (const float*)d_in[9];
    const float* b_hh_f     = (const float*)d_in[10];
    const float* w_ih_b     = (const float*)d_in[11];
    const float* w_hh_b     = (const float*)d_in[12];
    const float* b_ih_b     = (const float*)d_in[13];
    const float* b_hh_b     = (const float*)d_in[14];
    const float* h2t_w      = (const float*)d_in[15];
    const float* h2t_b      = (const float*)d_in[16];
    const float* trans      = (const float*)d_in[17];
    float* out = (float*)d_out;

    cudaFuncSetAttribute(k_lstm, cudaFuncAttributeMaxDynamicSharedMemorySize, LSTM_SMEM);

    k_prep<<<3 * CV_, 128>>>(char_table, conv_w);
    k_prep_w<<<2048, 128>>>(w_ih_f, w_ih_b);
    k_embed<<<B_ * S_, 128>>>(word_idxs, char_idxs, word_table, conv_b);
    dim3 g3(16, 256);   // n-tiles x m-tiles
    k_gemm_mma<<<g3, 256>>>(b_ih_f, b_hh_f, b_ih_b, b_hh_b);
    k_lstm<<<128, 256, LSTM_SMEM>>>(w_hh_f, w_hh_b);
    k_feats<<<(B_ * S_) / 8, 256>>>(h2t_w, h2t_b);
    k_viterbi<<<B_, 32>>>(mask, trans, out);
}

// round 14
// speedup vs baseline: 2.0516x; 1.6434x over previous
#include <cuda_runtime.h>
#include <cuda_bf16.h>

// ---------------- problem constants ----------------
constexpr int B_   = 128;
constexpr int S_   = 256;
constexpr int W_   = 20;
constexpr int WE_  = 300;
constexpr int CE_  = 50;
constexpr int CC_  = 100;
constexpr int CV_  = 100;
constexpr int H_   = 256;     // per-direction hidden
constexpr int DIN_ = 400;     // WE + CC
constexpr int T_   = 12;
constexpr int START_ = 9, STOP_ = 10, PAD_ = 11;

// ---------------- scratch (device globals; no allocation allowed) ----------
__device__ float g_P[3 * CV_ * CC_];            // [k][v][c] conv response table
__device__ __nv_bfloat16 g_xs_hi[S_ * B_ * DIN_];   // split embeddings (hi)
__device__ __nv_bfloat16 g_xs_lo[S_ * B_ * DIN_];   // split embeddings (lo)
__device__ __nv_bfloat16 g_w_hi[2048 * DIN_];       // split w_ih (f then b), hi
__device__ __nv_bfloat16 g_w_lo[2048 * DIN_];       // split w_ih, lo
__device__ float g_xproj[S_ * B_ * 2048];       // input projection, [s][b][2*1024]
__device__ float g_h[2][S_ * B_ * H_];          // lstm hidden, [dir][s][b][h]
__device__ __nv_bfloat16 g_hbs[2][2][2][B_][H_]; // [parity][dir][hi/lo][b][k]
__device__ float g_feats[S_ * B_ * T_];         // [s][b][t]
__device__ int   g_cnt[8];                      // group sync counters [dir*4+bt]

__device__ __forceinline__ float sigf(float x) { return 1.0f / (1.0f + expf(-x)); }

__device__ __forceinline__ void split_store(float v, __nv_bfloat16* hi, __nv_bfloat16* lo)
{
    __nv_bfloat16 h = __float2bfloat16(v);
    *hi = h;
    *lo = __float2bfloat16(v - __bfloat162float(h));
}

// ---------------- K1: precompute conv response table + reset counters ------
__global__ void k_prep(const float* __restrict__ char_table,
                       const float* __restrict__ conv_w)
{
    int blk = blockIdx.x;            // 0..299
    int k = blk / CV_, v = blk % CV_;
    int c = threadIdx.x;
    if (blk == 0 && c < 8) g_cnt[c] = 0;
    if (c < CC_) {
        float s = 0.f;
        #pragma unroll 10
        for (int e = 0; e < CE_; e++)
            s += char_table[v * CE_ + e] * conv_w[c * CE_ * 3 + e * 3 + k];
        g_P[(k * CV_ + v) * CC_ + c] = s;
    }
}

// ---------------- K1b: split w_ih into bf16 hi/lo --------------------------
__global__ void k_prep_w(const float* __restrict__ wf, const float* __restrict__ wb)
{
    int n = blockIdx.x;              // 0..2047
    const float* src = (n < 1024) ? (wf + n * DIN_) : (wb + (n - 1024) * DIN_);
    for (int i = threadIdx.x; i < DIN_; i += blockDim.x)
        split_store(src[i], &g_w_hi[n * DIN_ + i], &g_w_lo[n * DIN_ + i]);
}

// ---------------- K2: word-emb gather + char conv/relu/maxpool -------------
__global__ void k_embed(const int* __restrict__ word_idxs,
                        const int* __restrict__ char_idxs,
                        const float* __restrict__ word_table,
                        const float* __restrict__ conv_b)
{
    int bs = blockIdx.x;             // b*S + s
    int b = bs >> 8, s = bs & 255;
    int tid = threadIdx.x;
    __shared__ int ch[W_];
    int wi = word_idxs[b * S_ + s];
    size_t base = (size_t)(s * B_ + b) * DIN_;
    for (int i = tid; i < WE_; i += 128)
        split_store(word_table[wi * WE_ + i], &g_xs_hi[base + i], &g_xs_lo[base + i]);
    if (tid < W_) ch[tid] = char_idxs[(b * S_ + s) * W_ + tid];
    __syncthreads();
    if (tid < CC_) {
        int c = tid;
        float bb = conv_b[c];
        float m = -3.4e38f;
        #pragma unroll
        for (int w = 0; w < W_; w++) {
            float v = bb;
            if (w > 0)      v += g_P[(0 * CV_ + ch[w - 1]) * CC_ + c];
            v += g_P[(1 * CV_ + ch[w]) * CC_ + c];
            if (w < W_ - 1) v += g_P[(2 * CV_ + ch[w + 1]) * CC_ + c];
            m = fmaxf(m, v);
        }
        float val = fmaxf(m, 0.0f);  // max of relu == relu of max
        split_store(val, &g_xs_hi[base + WE_ + c], &g_xs_lo[base + WE_ + c]);
    }
}

// ---------------- shared MMA helper ----------------------------------------
constexpr int GSTR = 24;  // padded smem row (bf16 elems) per 16-k chunk

__device__ __forceinline__ void mma16816(float* c, const unsigned* a, const unsigned* b)
{
    asm volatile(
        "mma.sync.aligned.m16n8k16.row.col.f32.bf16.bf16.f32 "
        "{%0,%1,%2,%3}, {%4,%5,%6,%7}, {%8,%9}, {%0,%1,%2,%3};\n"
        : "+f"(c[0]), "+f"(c[1]), "+f"(c[2]), "+f"(c[3])
        : "r"(a[0]), "r"(a[1]), "r"(a[2]), "r"(a[3]), "r"(b[0]), "r"(b[1]));
}

// ---------------- K3: input projection GEMM (tensor cores, split-bf16) -----
__global__ void __launch_bounds__(256) k_gemm_mma(
    const float* __restrict__ bihf, const float* __restrict__ bhhf,
    const float* __restrict__ bihb, const float* __restrict__ bhhb)
{
    __shared__ __nv_bfloat16 sAhi[128 * GSTR], sAlo[128 * GSTR];
    __shared__ __nv_bfloat16 sBhi[128 * GSTR], sBlo[128 * GSTR];
    __shared__ float sBias[128];

    int tid = threadIdx.x;
    int m0 = blockIdx.y * 128;
    int n0 = blockIdx.x * 128;
    int wid = tid >> 5, lane = tid & 31;
    int warp_m = wid >> 2, warp_n = wid & 3;

    if (tid < 128) {
        int n2 = n0 + tid;
        sBias[tid] = (n2 < 1024) ? (bihf[n2] + bhhf[n2])
                                 : (bihb[n2 - 1024] + bhhb[n2 - 1024]);
    }

    int r = tid >> 1, part = tid & 1;
    size_t a_off = (size_t)(m0 + r) * DIN_ + part * 8;
    size_t b_off = (size_t)(n0 + r) * DIN_ + part * 8;
    int s_off = r * GSTR + part * 8;

    float acc[4][4][4];
    #pragma unroll
    for (int mi = 0; mi < 4; mi++)
        #pragma unroll
        for (int ni = 0; ni < 4; ni++)
            #pragma unroll
            for (int q = 0; q < 4; q++) acc[mi][ni][q] = 0.f;

    int qr = lane >> 2, kp = (lane & 3) * 2;

    for (int k0 = 0; k0 < DIN_; k0 += 16) {
        uint4 vah = *(const uint4*)&g_xs_hi[a_off + k0];
        uint4 val = *(const uint4*)&g_xs_lo[a_off + k0];
        uint4 vbh = *(const uint4*)&g_w_hi[b_off + k0];
        uint4 vbl = *(const uint4*)&g_w_lo[b_off + k0];
        __syncthreads();
        *(uint4*)&sAhi[s_off] = vah;
        *(uint4*)&sAlo[s_off] = val;
        *(uint4*)&sBhi[s_off] = vbh;
        *(uint4*)&sBlo[s_off] = vbl;
        __syncthreads();

        unsigned ahi[4][4], alo[4][4], bhi[4][2], blo[4][2];
        #pragma unroll
        for (int mi = 0; mi < 4; mi++) {
            int rr = warp_m * 64 + mi * 16 + qr;
            ahi[mi][0] = *(const unsigned*)&sAhi[rr * GSTR + kp];
            ahi[mi][1] = *(const unsigned*)&sAhi[(rr + 8) * GSTR + kp];
            ahi[mi][2] = *(const unsigned*)&sAhi[rr * GSTR + kp + 8];
            ahi[mi][3] = *(const unsigned*)&sAhi[(rr + 8) * GSTR + kp + 8];
            alo[mi][0] = *(const unsigned*)&sAlo[rr * GSTR + kp];
            alo[mi][1] = *(const unsigned*)&sAlo[(rr + 8) * GSTR + kp];
            alo[mi][2] = *(const unsigned*)&sAlo[rr * GSTR + kp + 8];
            alo[mi][3] = *(const unsigned*)&sAlo[(rr + 8) * GSTR + kp + 8];
        }
        #pragma unroll
        for (int ni = 0; ni < 4; ni++) {
            int cc = warp_n * 32 + ni * 8 + qr;
            bhi[ni][0] = *(const unsigned*)&sBhi[cc * GSTR + kp];
            bhi[ni][1] = *(const unsigned*)&sBhi[cc * GSTR + kp + 8];
            blo[ni][0] = *(const unsigned*)&sBlo[cc * GSTR + kp];
            blo[ni][1] = *(const unsigned*)&sBlo[cc * GSTR + kp + 8];
        }
        #pragma unroll
        for (int mi = 0; mi < 4; mi++)
            #pragma unroll
            for (int ni = 0; ni < 4; ni++)
                mma16816(acc[mi][ni], ahi[mi], bhi[ni]);
        #pragma unroll
        for (int mi = 0; mi < 4; mi++)
            #pragma unroll
            for (int ni = 0; ni < 4; ni++)
                mma16816(acc[mi][ni], ahi[mi], blo[ni]);
        #pragma unroll
        for (int mi = 0; mi < 4; mi++)
            #pragma unroll
            for (int ni = 0; ni < 4; ni++)
                mma16816(acc[mi][ni], alo[mi], bhi[ni]);
    }

    #pragma unroll
    for (int mi = 0; mi < 4; mi++) {
        int rr = warp_m * 64 + mi * 16 + qr;
        #pragma unroll
        for (int ni = 0; ni < 4; ni++) {
            int cc = warp_n * 32 + ni * 8 + kp;
            float b0 = sBias[cc], b1 = sBias[cc + 1];
            float* p = &g_xproj[(size_t)(m0 + rr) * 2048 + n0 + cc];
            float2 v0 = make_float2(acc[mi][ni][0] + b0, acc[mi][ni][1] + b1);
            float2 v1 = make_float2(acc[mi][ni][2] + b0, acc[mi][ni][3] + b1);
            *(float2*)p = v0;
            *(float2*)(p + 8 * 2048) = v1;
        }
    }
}

// ---------------- K4: bidirectional LSTM recurrence (tensor cores) ---------
// Grid: 128 CTAs = dir(2) x batch-tile(4, 32 each) x h-slice(16, 16 units).
// Each CTA: resident bf16 hi/lo w_hh slice [64 gate-rows x 256] (98KB smem).
// Per step: gates[32b x 64g] = xproj + h(t-1) @ w_hh^T via split-bf16 MMA.
// h carried between steps as bf16 hi/lo in parity-double-buffered global.
// Group sync (16 CTAs per (dir,bt)) via red.release / ld.acquire counter.
constexpr int GSTRG = 70;  // gate transpose buffer stride (even -> float2 ok)
constexpr int LSTM_SMEM = (2 * 16 * 64 * GSTR + 2 * 16 * 32 * GSTR) * 2
                        + 32 * GSTRG * 4;   // 156416 B

__global__ void __launch_bounds__(256) k_lstm_mma(const float* __restrict__ whhf,
                                                  const float* __restrict__ whhb)
{
    extern __shared__ char smraw[];
    __nv_bfloat16* sWhi = (__nv_bfloat16*)smraw;          // [16][64][GSTR]
    __nv_bfloat16* sWlo = sWhi + 16 * 64 * GSTR;
    __nv_bfloat16* sAhi = sWlo + 16 * 64 * GSTR;          // [16][32][GSTR]
    __nv_bfloat16* sAlo = sAhi + 16 * 32 * GSTR;
    float* sG = (float*)(sAlo + 16 * 32 * GSTR);          // [32][GSTRG]

    int tid  = threadIdx.x;
    int dir  = blockIdx.x >> 6;
    int bt   = (blockIdx.x >> 4) & 3;
    int hs   = blockIdx.x & 15;
    int lane = tid & 31;
    int wid  = tid >> 5;
    int wm   = wid >> 2, wn = wid & 3;     // 2 x 4 warp grid; wn == gate index
    int qr   = lane >> 2, kp = (lane & 3) * 2;
    int bsub = tid & 31;
    int uq   = tid >> 5;                   // unit pair owner: units uq*2, uq*2+1
    const float* whh = dir ? whhb : whhf;

    // resident weights: local row r = g*16+u -> global row g*256 + hs*16 + u
    for (int idx = tid; idx < 64 * 256; idx += 256) {
        int row = idx >> 8, k = idx & 255;
        int g = row >> 4, u = row & 15;
        float w = whh[(g * H_ + hs * 16 + u) * H_ + k];
        int off = (k >> 4) * 64 * GSTR + row * GSTR + (k & 15);
        __nv_bfloat16 h = __float2bfloat16(w);
        sWhi[off] = h;
        sWlo[off] = __float2bfloat16(w - __bfloat162float(h));
    }

    int bglob = bt * 32 + bsub;
    int ub0 = hs * 16 + uq * 2;
    // zero-init h(-1): parity 1
    {
        __nv_bfloat162 z; z.x = __float2bfloat16(0.f); z.y = z.x;
        *(__nv_bfloat162*)&g_hbs[1][dir][0][bglob][ub0] = z;
        *(__nv_bfloat162*)&g_hbs[1][dir][1][bglob][ub0] = z;
    }
    __syncthreads();
    int* cntp = &g_cnt[dir * 4 + bt];
    if (tid == 0)
        asm volatile("red.release.gpu.global.add.s32 [%0], %1;"
                     :: "l"(cntp), "r"(1) : "memory");

    float c0 = 0.f, c1 = 0.f;

    for (int t = 0; t < S_; t++) {
        int s = dir ? (S_ - 1 - t) : t;
        if (tid == 0) {
            int target = 16 * (t + 1), v;
            do {
                asm volatile("ld.acquire.gpu.global.s32 %0, [%1];"
                             : "=r"(v) : "l"(cntp) : "memory");
            } while (v < target);
        }
        __syncthreads();

        // accumulator init from xproj (independent of h; issue early)
        float acc[2][4];
        {
            const float* xpb = &g_xproj[(size_t)(s * B_ + bt * 32 + wm * 16 + qr) * 2048
                                        + dir * 1024 + wn * 256 + hs * 16 + kp];
            #pragma unroll
            for (int ni = 0; ni < 2; ni++) {
                float2 v0 = *(const float2*)(xpb + ni * 8);
                float2 v1 = *(const float2*)(xpb + ni * 8 + 8 * 2048);
                acc[ni][0] = v0.x; acc[ni][1] = v0.y;
                acc[ni][2] = v1.x; acc[ni][3] = v1.y;
            }
        }

        // stage h(t-1) [parity (t+1)&1] into smem (L2 loads, skip stale L1)
        int par = (t + 1) & 1;
        for (int i = tid; i < 1024; i += 256) {
            int b = i >> 5;
            int k8 = (i & 31) * 8;
            int off = (k8 >> 4) * 32 * GSTR + b * GSTR + (k8 & 15);
            uint4 vh = __ldcg((const uint4*)&g_hbs[par][dir][0][bt * 32 + b][k8]);
            uint4 vl = __ldcg((const uint4*)&g_hbs[par][dir][1][bt * 32 + b][k8]);
            *(uint4*)&sAhi[off] = vh;
            *(uint4*)&sAlo[off] = vl;
        }
        __syncthreads();

        // 3-pass split MMA over K=256 (16 chunks)
        #pragma unroll
        for (int kc = 0; kc < 16; kc++) {
            const __nv_bfloat16* pA  = sAhi + kc * 32 * GSTR + (wm * 16 + qr) * GSTR + kp;
            const __nv_bfloat16* pAl = sAlo + kc * 32 * GSTR + (wm * 16 + qr) * GSTR + kp;
            unsigned ahi[4], alo[4];
            ahi[0] = *(const unsigned*)pA;
            ahi[1] = *(const unsigned*)(pA + 8 * GSTR);
            ahi[2] = *(const unsigned*)(pA + 8);
            ahi[3] = *(const unsigned*)(pA + 8 * GSTR + 8);
            alo[0] = *(const unsigned*)pAl;
            alo[1] = *(const unsigned*)(pAl + 8 * GSTR);
            alo[2] = *(const unsigned*)(pAl + 8);
            alo[3] = *(const unsigned*)(pAl + 8 * GSTR + 8);
            #pragma unroll
            for (int ni = 0; ni < 2; ni++) {
                int cbase = kc * 64 * GSTR + (wn * 16 + ni * 8 + qr) * GSTR + kp;
                unsigned bh[2], bl[2];
                bh[0] = *(const unsigned*)&sWhi[cbase];
                bh[1] = *(const unsigned*)&sWhi[cbase + 8];
                bl[0] = *(const unsigned*)&sWlo[cbase];
                bl[1] = *(const unsigned*)&sWlo[cbase + 8];
                mma16816(acc[ni], ahi, bh);
                mma16816(acc[ni], ahi, bl);
                mma16816(acc[ni], alo, bh);
            }
        }

        // transpose gates through smem to per-(batch,unit) threads
        #pragma unroll
        for (int ni = 0; ni < 2; ni++) {
            int col = wn * 16 + ni * 8 + kp;
            *(float2*)&sG[(wm * 16 + qr) * GSTRG + col]     = make_float2(acc[ni][0], acc[ni][1]);
            *(float2*)&sG[(wm * 16 + qr + 8) * GSTRG + col] = make_float2(acc[ni][2], acc[ni][3]);
        }
        __syncthreads();

        // activation; c carried in registers by thread (bsub, uq)
        float* h_out = &g_h[dir][(size_t)(s * B_ + bglob) * H_ + ub0];
        __nv_bfloat162 hhi, hlo;
        float hv0, hv1;
        {
            const float* gr = &sG[bsub * GSTRG];
            #pragma unroll
            for (int uu = 0; uu < 2; uu++) {
                int u = uq * 2 + uu;
                float ig = sigf(gr[0 * 16 + u]);
                float fg = sigf(gr[1 * 16 + u]);
                float gg = tanhf(gr[2 * 16 + u]);
                float og = sigf(gr[3 * 16 + u]);
                float cc = (uu ? c1 : c0);
                cc = fg * cc + ig * gg;
                if (uu) c1 = cc; else c0 = cc;
                float hv = og * tanhf(cc);
                if (uu) hv1 = hv; else hv0 = hv;
            }
            __nv_bfloat16 h0 = __float2bfloat16(hv0);
            __nv_bfloat16 h1 = __float2bfloat16(hv1);
            hhi.x = h0; hhi.y = h1;
            hlo.x = __float2bfloat16(hv0 - __bfloat162float(h0));
            hlo.y = __float2bfloat16(hv1 - __bfloat162float(h1));
        }
        *(__nv_bfloat162*)&g_hbs[t & 1][dir][0][bglob][ub0] = hhi;
        *(__nv_bfloat162*)&g_hbs[t & 1][dir][1][bglob][ub0] = hlo;
        *(float2*)h_out = make_float2(hv0, hv1);

        __syncthreads();
        if (tid == 0)
            asm volatile("red.release.gpu.global.add.s32 [%0], %1;"
                         :: "l"(cntp), "r"(1) : "memory");
    }
}

// ---------------- K5: feats = [h_f, h_b] @ h2t_w^T + h2t_b -----------------
__global__ void __launch_bounds__(256) k_feats(const float* __restrict__ h2t_w,
                                               const float* __restrict__ h2t_b)
{
    __shared__ float w_s[T_ * 512];
    __shared__ float b_s[T_];
    int tid = threadIdx.x;
    for (int i = tid; i < T_ * 512; i += 256) w_s[i] = h2t_w[i];
    if (tid < T_) b_s[tid] = h2t_b[tid];
    __syncthreads();
    int wid = tid >> 5, lane = tid & 31;
    int m = blockIdx.x * 8 + wid;          // m = s*B + b
    const float* hf  = &g_h[0][(size_t)m * H_];
    const float* hbk = &g_h[1][(size_t)m * H_];
    float hr[16];
    #pragma unroll
    for (int i = 0; i < 8; i++) hr[i]     = hf[lane + 32 * i];
    #pragma unroll
    for (int i = 0; i < 8; i++) hr[8 + i] = hbk[lane + 32 * i];
    for (int t = 0; t < T_; t++) {
        float a = 0.f;
        #pragma unroll
        for (int i = 0; i < 8; i++)
            a = fmaf(hr[i], w_s[t * 512 + lane + 32 * i], a);
        #pragma unroll
        for (int i = 0; i < 8; i++)
            a = fmaf(hr[8 + i], w_s[t * 512 + 256 + lane + 32 * i], a);
        #pragma unroll
        for (int off = 16; off; off >>= 1)
            a += __shfl_xor_sync(0xffffffff, a, off);
        if (lane == 0) g_feats[m * T_ + t] = a + b_s[t];
    }
}

// ---------------- K6: batched Viterbi + backtrace --------------------------
__global__ void k_viterbi(const int* __restrict__ mask,
                          const float* __restrict__ trans,
                          float* __restrict__ out)
{
    int b = blockIdx.x;
    int lane = threadIdx.x;                 // 32 threads
    __shared__ float tr[T_ * T_];
    __shared__ float alpha[T_];
    __shared__ float alpha2[T_];
    __shared__ unsigned char bps[S_ * T_];
    __shared__ int msk[S_];
    for (int i = lane; i < T_ * T_; i += 32) tr[i] = trans[i];
    for (int i = lane; i < S_; i += 32) msk[i] = mask[b * S_ + i];
    if (lane < T_) alpha[lane] = (lane == START_) ? 0.0f : -10000.0f;
    __syncwarp();
    for (int s = 0; s < S_; s++) {
        float na = 0.f; int bi = 0;
        if (lane < T_) {
            float f = g_feats[(s * B_ + b) * T_ + lane];
            float best = -3.4e38f;
            #pragma unroll
            for (int p = 0; p < T_; p++) {
                float sc = (alpha[p] + tr[p * T_ + lane]) + f;  // same assoc as ref
                if (sc > best) { best = sc; bi = p; }           // first-max tie-break
            }
            bps[s * T_ + lane] = (unsigned char)bi;
            na = msk[s] ? best : alpha[lane];
        }
        __syncwarp();
        if (lane < T_) alpha[lane] = na;
        __syncwarp();
    }
    if (lane < T_) alpha2[lane] = alpha[lane] + tr[STOP_ * T_ + lane];
    __syncwarp();
    if (lane == 0) {
        float best = -3.4e38f; int bl = 0;
        for (int t = 0; t < T_; t++)
            if (alpha2[t] > best) { best = alpha2[t]; bl = t; }
        out[b] = best;
        int tag = bl;
        for (int i = S_ - 1; i >= 0; i--) {
            int valid = msk[i];
            int o = valid ? tag : PAD_;
            out[B_ + b * S_ + i] = (float)o;
            int prev = bps[i * T_ + tag];
            tag = valid ? prev : tag;
        }
    }
}

// ---------------- launch ---------------------------------------------------
extern "C" void kernel_launch(void* const* d_in, const int* in_sizes, int n_in,
                              void* d_out, int out_size)
{
    const int*   word_idxs  = (const int*)d_in[0];
    const int*   char_idxs  = (const int*)d_in[1];
    const int*   mask       = (const int*)d_in[2];
    const float* word_table = (const float*)d_in[3];
    const float* char_table = (const float*)d_in[4];
    const float* conv_w     = (const float*)d_in[5];
    const float* conv_b     = (const float*)d_in[6];
    const float* w_ih_f     = (const float*)d_in[7];
    const float* w_hh_f     = (const float*)d_in[8];
    const float* b_ih_f     = (const float*)d_in[9];
    const float* b_hh_f     = (const float*)d_in[10];
    const float* w_ih_b     = (const float*)d_in[11];
    const float* w_hh_b     = (const float*)d_in[12];
    const float* b_ih_b     = (const float*)d_in[13];
    const float* b_hh_b     = (const float*)d_in[14];
    const float* h2t_w      = (const float*)d_in[15];
    const float* h2t_b      = (const float*)d_in[16];
    const float* trans      = (const float*)d_in[17];
    float* out = (float*)d_out;

    cudaFuncSetAttribute(k_lstm_mma, cudaFuncAttributeMaxDynamicSharedMemorySize, LSTM_SMEM);

    k_prep<<<3 * CV_, 128>>>(char_table, conv_w);
    k_prep_w<<<2048, 128>>>(w_ih_f, w_ih_b);
    k_embed<<<B_ * S_, 128>>>(word_idxs, char_idxs, word_table, conv_b);
    dim3 g3(16, 256);   // n-tiles x m-tiles
    k_gemm_mma<<<g3, 256>>>(b_ih_f, b_hh_f, b_ih_b, b_hh_b);
    k_lstm_mma<<<128, 256, LSTM_SMEM>>>(w_hh_f, w_hh_b);
    k_feats<<<(B_ * S_) / 8, 256>>>(h2t_w, h2t_b);
    k_viterbi<<<B_, 32>>>(mask, trans, out);
}

// round 15
// speedup vs baseline: 2.1915x; 1.0682x over previous
#include <cuda_runtime.h>
#include <cuda_bf16.h>

// ---------------- problem constants ----------------
constexpr int B_   = 128;
constexpr int S_   = 256;
constexpr int W_   = 20;
constexpr int WE_  = 300;
constexpr int CE_  = 50;
constexpr int CC_  = 100;
constexpr int CV_  = 100;
constexpr int H_   = 256;     // per-direction hidden
constexpr int DIN_ = 400;     // WE + CC
constexpr int T_   = 12;
constexpr int START_ = 9, STOP_ = 10, PAD_ = 11;

// ---------------- scratch (device globals; no allocation allowed) ----------
__device__ float g_P[3 * CV_ * CC_];            // [k][v][c] conv response table
__device__ __nv_bfloat16 g_xs_hi[S_ * B_ * DIN_];   // split embeddings (hi)
__device__ __nv_bfloat16 g_xs_lo[S_ * B_ * DIN_];   // split embeddings (lo)
__device__ __nv_bfloat16 g_w_hi[2048 * DIN_];       // split w_ih (f then b), hi
__device__ __nv_bfloat16 g_w_lo[2048 * DIN_];       // split w_ih, lo
__device__ float g_xproj[S_ * B_ * 2048];       // input projection, [s][b][2*1024]
__device__ float g_h[2][S_ * B_ * H_];          // lstm hidden, [dir][s][b][h]
__device__ __nv_bfloat16 g_hbs[2][2][2][B_][H_]; // [parity][dir][hi/lo][b][k]
__device__ float g_feats[S_ * B_ * T_];         // [s][b][t]
__device__ int   g_cnt[8];                      // group sync counters [dir*4+bt]

__device__ __forceinline__ float sigf(float x) { return 1.0f / (1.0f + expf(-x)); }

__device__ __forceinline__ void split_store(float v, __nv_bfloat16* hi, __nv_bfloat16* lo)
{
    __nv_bfloat16 h = __float2bfloat16(v);
    *hi = h;
    *lo = __float2bfloat16(v - __bfloat162float(h));
}

__device__ __forceinline__ void cpasync16(void* smem_dst, const void* gsrc)
{
    unsigned s = (unsigned)__cvta_generic_to_shared(smem_dst);
    asm volatile("cp.async.cg.shared.global [%0], [%1], 16;\n" :: "r"(s), "l"(gsrc));
}

// ---------------- K1: precompute conv response table + reset counters ------
__global__ void k_prep(const float* __restrict__ char_table,
                       const float* __restrict__ conv_w)
{
    int blk = blockIdx.x;            // 0..299
    int k = blk / CV_, v = blk % CV_;
    int c = threadIdx.x;
    if (blk == 0 && c < 8) g_cnt[c] = 0;
    if (c < CC_) {
        float s = 0.f;
        #pragma unroll 10
        for (int e = 0; e < CE_; e++)
            s += char_table[v * CE_ + e] * conv_w[c * CE_ * 3 + e * 3 + k];
        g_P[(k * CV_ + v) * CC_ + c] = s;
    }
}

// ---------------- K1b: split w_ih into bf16 hi/lo --------------------------
__global__ void k_prep_w(const float* __restrict__ wf, const float* __restrict__ wb)
{
    int n = blockIdx.x;              // 0..2047
    const float* src = (n < 1024) ? (wf + n * DIN_) : (wb + (n - 1024) * DIN_);
    for (int i = threadIdx.x; i < DIN_; i += blockDim.x)
        split_store(src[i], &g_w_hi[n * DIN_ + i], &g_w_lo[n * DIN_ + i]);
}

// ---------------- K2: word-emb gather + char conv/relu/maxpool -------------
__global__ void k_embed(const int* __restrict__ word_idxs,
                        const int* __restrict__ char_idxs,
                        const float* __restrict__ word_table,
                        const float* __restrict__ conv_b)
{
    int bs = blockIdx.x;             // b*S + s
    int b = bs >> 8, s = bs & 255;
    int tid = threadIdx.x;
    __shared__ int ch[W_];
    int wi = word_idxs[b * S_ + s];
    size_t base = (size_t)(s * B_ + b) * DIN_;
    for (int i = tid; i < WE_; i += 128)
        split_store(word_table[wi * WE_ + i], &g_xs_hi[base + i], &g_xs_lo[base + i]);
    if (tid < W_) ch[tid] = char_idxs[(b * S_ + s) * W_ + tid];
    __syncthreads();
    if (tid < CC_) {
        int c = tid;
        float bb = conv_b[c];
        float m = -3.4e38f;
        #pragma unroll
        for (int w = 0; w < W_; w++) {
            float v = bb;
            if (w > 0)      v += g_P[(0 * CV_ + ch[w - 1]) * CC_ + c];
            v += g_P[(1 * CV_ + ch[w]) * CC_ + c];
            if (w < W_ - 1) v += g_P[(2 * CV_ + ch[w + 1]) * CC_ + c];
            m = fmaxf(m, v);
        }
        float val = fmaxf(m, 0.0f);  // max of relu == relu of max
        split_store(val, &g_xs_hi[base + WE_ + c], &g_xs_lo[base + WE_ + c]);
    }
}

// ---------------- shared MMA helper ----------------------------------------
constexpr int GSTR = 24;  // padded smem row (bf16 elems) per 16-k chunk

__device__ __forceinline__ void mma16816(float* c, const unsigned* a, const unsigned* b)
{
    asm volatile(
        "mma.sync.aligned.m16n8k16.row.col.f32.bf16.bf16.f32 "
        "{%0,%1,%2,%3}, {%4,%5,%6,%7}, {%8,%9}, {%0,%1,%2,%3};\n"
        : "+f"(c[0]), "+f"(c[1]), "+f"(c[2]), "+f"(c[3])
        : "r"(a[0]), "r"(a[1]), "r"(a[2]), "r"(a[3]), "r"(b[0]), "r"(b[1]));
}

// ---------------- K3: input projection GEMM (cp.async 2-stage pipeline) ----
// C[m, n] = xs[m, :] . w_ih[n, :] + (b_ih + b_hh)[n]
// m = s*B+b (32768), n in [0,2048). CTA 128x128, BK=16, 8 warps (2m x 4n).
__global__ void __launch_bounds__(256) k_gemm_mma(
    const float* __restrict__ bihf, const float* __restrict__ bhhf,
    const float* __restrict__ bihb, const float* __restrict__ bhhb)
{
    __shared__ __nv_bfloat16 sAhi[2][128 * GSTR], sAlo[2][128 * GSTR];
    __shared__ __nv_bfloat16 sBhi[2][128 * GSTR], sBlo[2][128 * GSTR];
    __shared__ float sBias[128];

    int tid = threadIdx.x;
    int m0 = blockIdx.y * 128;
    int n0 = blockIdx.x * 128;
    int wid = tid >> 5, lane = tid & 31;
    int warp_m = wid >> 2, warp_n = wid & 3;

    if (tid < 128) {
        int n2 = n0 + tid;
        sBias[tid] = (n2 < 1024) ? (bihf[n2] + bhhf[n2])
                                 : (bihb[n2 - 1024] + bhhb[n2 - 1024]);
    }

    int r = tid >> 1, part = tid & 1;
    size_t a_off = (size_t)(m0 + r) * DIN_ + part * 8;
    size_t b_off = (size_t)(n0 + r) * DIN_ + part * 8;
    int s_off = r * GSTR + part * 8;

    float acc[4][4][4];
    #pragma unroll
    for (int mi = 0; mi < 4; mi++)
        #pragma unroll
        for (int ni = 0; ni < 4; ni++)
            #pragma unroll
            for (int q = 0; q < 4; q++) acc[mi][ni][q] = 0.f;

    int qr = lane >> 2, kp = (lane & 3) * 2;
    constexpr int NIT = DIN_ / 16;   // 25

    // prologue: stage chunk 0
    cpasync16(&sAhi[0][s_off], &g_xs_hi[a_off]);
    cpasync16(&sAlo[0][s_off], &g_xs_lo[a_off]);
    cpasync16(&sBhi[0][s_off], &g_w_hi[b_off]);
    cpasync16(&sBlo[0][s_off], &g_w_lo[b_off]);
    asm volatile("cp.async.commit_group;\n" ::: "memory");

    for (int kc = 0; kc < NIT; kc++) {
        int cur = kc & 1;
        if (kc + 1 < NIT) {
            int nxt = cur ^ 1, k0 = (kc + 1) * 16;
            cpasync16(&sAhi[nxt][s_off], &g_xs_hi[a_off + k0]);
            cpasync16(&sAlo[nxt][s_off], &g_xs_lo[a_off + k0]);
            cpasync16(&sBhi[nxt][s_off], &g_w_hi[b_off + k0]);
            cpasync16(&sBlo[nxt][s_off], &g_w_lo[b_off + k0]);
            asm volatile("cp.async.commit_group;\n" ::: "memory");
            asm volatile("cp.async.wait_group 1;\n" ::: "memory");
        } else {
            asm volatile("cp.async.wait_group 0;\n" ::: "memory");
        }
        __syncthreads();

        unsigned ahi[4][4], alo[4][4], bhi[4][2], blo[4][2];
        #pragma unroll
        for (int mi = 0; mi < 4; mi++) {
            int rr = warp_m * 64 + mi * 16 + qr;
            ahi[mi][0] = *(const unsigned*)&sAhi[cur][rr * GSTR + kp];
            ahi[mi][1] = *(const unsigned*)&sAhi[cur][(rr + 8) * GSTR + kp];
            ahi[mi][2] = *(const unsigned*)&sAhi[cur][rr * GSTR + kp + 8];
            ahi[mi][3] = *(const unsigned*)&sAhi[cur][(rr + 8) * GSTR + kp + 8];
            alo[mi][0] = *(const unsigned*)&sAlo[cur][rr * GSTR + kp];
            alo[mi][1] = *(const unsigned*)&sAlo[cur][(rr + 8) * GSTR + kp];
            alo[mi][2] = *(const unsigned*)&sAlo[cur][rr * GSTR + kp + 8];
            alo[mi][3] = *(const unsigned*)&sAlo[cur][(rr + 8) * GSTR + kp + 8];
        }
        #pragma unroll
        for (int ni = 0; ni < 4; ni++) {
            int cc = warp_n * 32 + ni * 8 + qr;
            bhi[ni][0] = *(const unsigned*)&sBhi[cur][cc * GSTR + kp];
            bhi[ni][1] = *(const unsigned*)&sBhi[cur][cc * GSTR + kp + 8];
            blo[ni][0] = *(const unsigned*)&sBlo[cur][cc * GSTR + kp];
            blo[ni][1] = *(const unsigned*)&sBlo[cur][cc * GSTR + kp + 8];
        }
        #pragma unroll
        for (int mi = 0; mi < 4; mi++)
            #pragma unroll
            for (int ni = 0; ni < 4; ni++)
                mma16816(acc[mi][ni], ahi[mi], bhi[ni]);
        #pragma unroll
        for (int mi = 0; mi < 4; mi++)
            #pragma unroll
            for (int ni = 0; ni < 4; ni++)
                mma16816(acc[mi][ni], ahi[mi], blo[ni]);
        #pragma unroll
        for (int mi = 0; mi < 4; mi++)
            #pragma unroll
            for (int ni = 0; ni < 4; ni++)
                mma16816(acc[mi][ni], alo[mi], bhi[ni]);
        __syncthreads();
    }

    #pragma unroll
    for (int mi = 0; mi < 4; mi++) {
        int rr = warp_m * 64 + mi * 16 + qr;
        #pragma unroll
        for (int ni = 0; ni < 4; ni++) {
            int cc = warp_n * 32 + ni * 8 + kp;
            float b0 = sBias[cc], b1 = sBias[cc + 1];
            float* p = &g_xproj[(size_t)(m0 + rr) * 2048 + n0 + cc];
            float2 v0 = make_float2(acc[mi][ni][0] + b0, acc[mi][ni][1] + b1);
            float2 v1 = make_float2(acc[mi][ni][2] + b0, acc[mi][ni][3] + b1);
            *(float2*)p = v0;
            *(float2*)(p + 8 * 2048) = v1;
        }
    }
}

// ---------------- K4: bidirectional LSTM recurrence (tensor cores) ---------
// Grid: 128 CTAs = dir(2) x batch-tile(4, 32 each) x h-slice(16, 16 units).
// Resident bf16 hi/lo w_hh slice in smem, GATE-INTERLEAVED rows (r = u*4+g)
// so one n=8 MMA block yields all 4 gates of 2 units; a shfl.xor(1) butterfly
// delivers the full gate quad per (batch,unit) to one lane (no smem transpose).
// h carried between steps as bf16 hi/lo in parity-double-buffered global.
// Group sync (16 CTAs per (dir,bt)) via red.release / ld.acquire counter.
constexpr int LSTM_SMEM = (2 * 16 * 64 * GSTR + 2 * 16 * 32 * GSTR) * 2;  // 147456 B

__global__ void __launch_bounds__(256) k_lstm_mma(const float* __restrict__ whhf,
                                                  const float* __restrict__ whhb)
{
    extern __shared__ char smraw[];
    __nv_bfloat16* sWhi = (__nv_bfloat16*)smraw;          // [16][64][GSTR]
    __nv_bfloat16* sWlo = sWhi + 16 * 64 * GSTR;
    __nv_bfloat16* sAhi = sWlo + 16 * 64 * GSTR;          // [16][32][GSTR]
    __nv_bfloat16* sAlo = sAhi + 16 * 32 * GSTR;

    int tid  = threadIdx.x;
    int dir  = blockIdx.x >> 6;
    int bt   = (blockIdx.x >> 4) & 3;
    int hs   = blockIdx.x & 15;
    int lane = tid & 31;
    int wid  = tid >> 5;
    int wm   = wid >> 2, wn = wid & 3;     // 2 x 4 warp grid
    int qr   = lane >> 2, kp = (lane & 3) * 2;
    const float* whh = dir ? whhb : whhf;

    // resident weights, gate-interleaved: local row r' = u*4+g
    //   -> global gate row g*256 + hs*16 + u
    for (int idx = tid; idx < 64 * 256; idx += 256) {
        int row = idx >> 8, k = idx & 255;
        int u = row >> 2, g = row & 3;
        float w = whh[(g * H_ + hs * 16 + u) * H_ + k];
        int off = (k >> 4) * 64 * GSTR + row * GSTR + (k & 15);
        __nv_bfloat16 h = __float2bfloat16(w);
        sWhi[off] = h;
        sWlo[off] = __float2bfloat16(w - __bfloat162float(h));
    }

    // this lane's ownership (fixed across steps):
    //   batch_local = wm*16 + qr + (lane&1)*8
    //   unit(ni)    = hs*16 + wn*4 + ni*2 + ((lane&3)>>1)
    int blocal = wm * 16 + qr + (lane & 1) * 8;
    int bglob  = bt * 32 + blocal;
    int u0 = hs * 16 + wn * 4 + ((lane & 3) >> 1);   // ni=0 unit
    int u1 = u0 + 2;                                  // ni=1 unit
    // zero-init h(-1): parity 1
    g_hbs[1][dir][0][bglob][u0] = __float2bfloat16(0.f);
    g_hbs[1][dir][1][bglob][u0] = __float2bfloat16(0.f);
    g_hbs[1][dir][0][bglob][u1] = __float2bfloat16(0.f);
    g_hbs[1][dir][1][bglob][u1] = __float2bfloat16(0.f);
    __syncthreads();
    int* cntp = &g_cnt[dir * 4 + bt];
    if (tid == 0)
        asm volatile("red.release.gpu.global.add.s32 [%0], %1;"
                     :: "l"(cntp), "r"(1) : "memory");

    float creg[2] = {0.f, 0.f};

    for (int t = 0; t < S_; t++) {
        int s = dir ? (S_ - 1 - t) : t;

        // accumulator init from xproj — BEFORE the wait (independent of h)
        float acc[2][4];
        {
            const float* xb = &g_xproj[(size_t)(s * B_ + bt * 32) * 2048 + dir * 1024];
            #pragma unroll
            for (int ni = 0; ni < 2; ni++) {
                #pragma unroll
                for (int q = 0; q < 4; q++) {
                    int rowm = wm * 16 + qr + ((q >> 1) ? 8 : 0);
                    int coll = wn * 16 + ni * 8 + kp + (q & 1);   // = u*4+g local
                    int u = coll >> 2, g = coll & 3;
                    acc[ni][q] = xb[(size_t)rowm * 2048 + g * 256 + hs * 16 + u];
                }
            }
        }

        if (tid == 0) {
            int target = 16 * (t + 1), v;
            do {
                asm volatile("ld.acquire.gpu.global.s32 %0, [%1];"
                             : "=r"(v) : "l"(cntp) : "memory");
            } while (v < target);
        }
        __syncthreads();

        // stage h(t-1) [parity (t+1)&1] into smem (L2 loads, skip stale L1)
        int par = (t + 1) & 1;
        for (int i = tid; i < 1024; i += 256) {
            int b = i >> 5;
            int k8 = (i & 31) * 8;
            int off = (k8 >> 4) * 32 * GSTR + b * GSTR + (k8 & 15);
            uint4 vh = __ldcg((const uint4*)&g_hbs[par][dir][0][bt * 32 + b][k8]);
            uint4 vl = __ldcg((const uint4*)&g_hbs[par][dir][1][bt * 32 + b][k8]);
            *(uint4*)&sAhi[off] = vh;
            *(uint4*)&sAlo[off] = vl;
        }
        __syncthreads();

        // 3-pass split MMA over K=256 (16 chunks)
        #pragma unroll
        for (int kc = 0; kc < 16; kc++) {
            const __nv_bfloat16* pA  = sAhi + kc * 32 * GSTR + (wm * 16 + qr) * GSTR + kp;
            const __nv_bfloat16* pAl = sAlo + kc * 32 * GSTR + (wm * 16 + qr) * GSTR + kp;
            unsigned ahi[4], alo[4];
            ahi[0] = *(const unsigned*)pA;
            ahi[1] = *(const unsigned*)(pA + 8 * GSTR);
            ahi[2] = *(const unsigned*)(pA + 8);
            ahi[3] = *(const unsigned*)(pA + 8 * GSTR + 8);
            alo[0] = *(const unsigned*)pAl;
            alo[1] = *(const unsigned*)(pAl + 8 * GSTR);
            alo[2] = *(const unsigned*)(pAl + 8);
            alo[3] = *(const unsigned*)(pAl + 8 * GSTR + 8);
            #pragma unroll
            for (int ni = 0; ni < 2; ni++) {
                int cbase = kc * 64 * GSTR + (wn * 16 + ni * 8 + qr) * GSTR + kp;
                unsigned bh[2], bl[2];
                bh[0] = *(const unsigned*)&sWhi[cbase];
                bh[1] = *(const unsigned*)&sWhi[cbase + 8];
                bl[0] = *(const unsigned*)&sWlo[cbase];
                bl[1] = *(const unsigned*)&sWlo[cbase + 8];
                mma16816(acc[ni], ahi, bh);
                mma16816(acc[ni], ahi, bl);
                mma16816(acc[ni], alo, bh);
            }
        }

        // shfl butterfly: deliver all 4 gates of one (batch,unit) per lane.
        // even lane (lane&1==0) keeps row qr;  odd lane keeps row qr+8.
        int odd = lane & 1;
        #pragma unroll
        for (int ni = 0; ni < 2; ni++) {
            float s0 = __shfl_xor_sync(0xffffffff, odd ? acc[ni][0] : acc[ni][2], 1);
            float s1 = __shfl_xor_sync(0xffffffff, odd ? acc[ni][1] : acc[ni][3], 1);
            float gi = odd ? s0 : acc[ni][0];
            float gf = odd ? s1 : acc[ni][1];
            float gg = odd ? acc[ni][2] : s0;
            float go = odd ? acc[ni][3] : s1;
            float ig = sigf(gi);
            float fg = sigf(gf);
            float g2 = tanhf(gg);
            float og = sigf(go);
            float cc = fg * creg[ni] + ig * g2;
            creg[ni] = cc;
            float hv = og * tanhf(cc);
            int ug = ni ? u1 : u0;
            __nv_bfloat16 hh = __float2bfloat16(hv);
            g_hbs[t & 1][dir][0][bglob][ug] = hh;
            g_hbs[t & 1][dir][1][bglob][ug] =
                __float2bfloat16(hv - __bfloat162float(hh));
            g_h[dir][(size_t)(s * B_ + bglob) * H_ + ug] = hv;
        }

        __syncthreads();
        if (tid == 0)
            asm volatile("red.release.gpu.global.add.s32 [%0], %1;"
                         :: "l"(cntp), "r"(1) : "memory");
    }
}

// ---------------- K5: feats = [h_f, h_b] @ h2t_w^T + h2t_b -----------------
__global__ void __launch_bounds__(256) k_feats(const float* __restrict__ h2t_w,
                                               const float* __restrict__ h2t_b)
{
    __shared__ float w_s[T_ * 512];
    __shared__ float b_s[T_];
    int tid = threadIdx.x;
    for (int i = tid; i < T_ * 512; i += 256) w_s[i] = h2t_w[i];
    if (tid < T_) b_s[tid] = h2t_b[tid];
    __syncthreads();
    int wid = tid >> 5, lane = tid & 31;
    int m = blockIdx.x * 8 + wid;          // m = s*B + b
    const float* hf  = &g_h[0][(size_t)m * H_];
    const float* hbk = &g_h[1][(size_t)m * H_];
    float hr[16];
    #pragma unroll
    for (int i = 0; i < 8; i++) hr[i]     = hf[lane + 32 * i];
    #pragma unroll
    for (int i = 0; i < 8; i++) hr[8 + i] = hbk[lane + 32 * i];
    for (int t = 0; t < T_; t++) {
        float a = 0.f;
        #pragma unroll
        for (int i = 0; i < 8; i++)
            a = fmaf(hr[i], w_s[t * 512 + lane + 32 * i], a);
        #pragma unroll
        for (int i = 0; i < 8; i++)
            a = fmaf(hr[8 + i], w_s[t * 512 + 256 + lane + 32 * i], a);
        #pragma unroll
        for (int off = 16; off; off >>= 1)
            a += __shfl_xor_sync(0xffffffff, a, off);
        if (lane == 0) g_feats[m * T_ + t] = a + b_s[t];
    }
}

// ---------------- K6: batched Viterbi + backtrace --------------------------
__global__ void k_viterbi(const int* __restrict__ mask,
                          const float* __restrict__ trans,
                          float* __restrict__ out)
{
    int b = blockIdx.x;
    int lane = threadIdx.x;                 // 32 threads
    __shared__ float tr[T_ * T_];
    __shared__ float alpha[T_];
    __shared__ float alpha2[T_];
    __shared__ unsigned char bps[S_ * T_];
    __shared__ int msk[S_];
    for (int i = lane; i < T_ * T_; i += 32) tr[i] = trans[i];
    for (int i = lane; i < S_; i += 32) msk[i] = mask[b * S_ + i];
    if (lane < T_) alpha[lane] = (lane == START_) ? 0.0f : -10000.0f;
    __syncwarp();
    for (int s = 0; s < S_; s++) {
        float na = 0.f; int bi = 0;
        if (lane < T_) {
            float f = g_feats[(s * B_ + b) * T_ + lane];
            float best = -3.4e38f;
            #pragma unroll
            for (int p = 0; p < T_; p++) {
                float sc = (alpha[p] + tr[p * T_ + lane]) + f;  // same assoc as ref
                if (sc > best) { best = sc; bi = p; }           // first-max tie-break
            }
            bps[s * T_ + lane] = (unsigned char)bi;
            na = msk[s] ? best : alpha[lane];
        }
        __syncwarp();
        if (lane < T_) alpha[lane] = na;
        __syncwarp();
    }
    if (lane < T_) alpha2[lane] = alpha[lane] + tr[STOP_ * T_ + lane];
    __syncwarp();
    if (lane == 0) {
        float best = -3.4e38f; int bl = 0;
        for (int t = 0; t < T_; t++)
            if (alpha2[t] > best) { best = alpha2[t]; bl = t; }
        out[b] = best;
        int tag = bl;
        for (int i = S_ - 1; i >= 0; i--) {
            int valid = msk[i];
            int o = valid ? tag : PAD_;
            out[B_ + b * S_ + i] = (float)o;
            int prev = bps[i * T_ + tag];
            tag = valid ? prev : tag;
        }
    }
}

// ---------------- launch ---------------------------------------------------
extern "C" void kernel_launch(void* const* d_in, const int* in_sizes, int n_in,
                              void* d_out, int out_size)
{
    const int*   word_idxs  = (const int*)d_in[0];
    const int*   char_idxs  = (const int*)d_in[1];
    const int*   mask       = (const int*)d_in[2];
    const float* word_table = (const float*)d_in[3];
    const float* char_table = (const float*)d_in[4];
    const float* conv_w     = (const float*)d_in[5];
    const float* conv_b     = (const float*)d_in[6];
    const float* w_ih_f     = (const float*)d_in[7];
    const float* w_hh_f     = (const float*)d_in[8];
    const float* b_ih_f     = (const float*)d_in[9];
    const float* b_hh_f     = (const float*)d_in[10];
    const float* w_ih_b     = (const float*)d_in[11];
    const float* w_hh_b     = (const float*)d_in[12];
    const float* b_ih_b     = (const float*)d_in[13];
    const float* b_hh_b     = (const float*)d_in[14];
    const float* h2t_w      = (const float*)d_in[15];
    const float* h2t_b      = (const float*)d_in[16];
    const float* trans      = (const float*)d_in[17];
    float* out = (float*)d_out;

    cudaFuncSetAttribute(k_lstm_mma, cudaFuncAttributeMaxDynamicSharedMemorySize, LSTM_SMEM);

    k_prep<<<3 * CV_, 128>>>(char_table, conv_w);
    k_prep_w<<<2048, 128>>>(w_ih_f, w_ih_b);
    k_embed<<<B_ * S_, 128>>>(word_idxs, char_idxs, word_table, conv_b);
    dim3 g3(16, 256);   // n-tiles x m-tiles
    k_gemm_mma<<<g3, 256>>>(b_ih_f, b_hh_f, b_ih_b, b_hh_b);
    k_lstm_mma<<<128, 256, LSTM_SMEM>>>(w_hh_f, w_hh_b);
    k_feats<<<(B_ * S_) / 8, 256>>>(h2t_w, h2t_b);
    k_viterbi<<<B_, 32>>>(mask, trans, out);
}